// round 12
// baseline (speedup 1.0000x reference)
#include <cuda_runtime.h>
#include <cstdio>

#define BATCH   1024
#define IN_DIM  4096
#define HV      8192
#define NQ      13
#define DEPTH   3
#define NANG    (NQ*DEPTH)   // 39 angles
#define NTAP    (NANG+1)     // degree-39 polynomial -> 40 taps

// Scratch (no allocations allowed -> __device__ globals)
__device__ float g_classical[(size_t)BATCH*HV];      // 32 MB
__device__ float g_inv_norm[BATCH];
__device__ float g_alpha_re[NTAP];
__device__ float g_alpha_im[NTAP];

// ---------------------------------------------------------------------------
// 1) Collapse 39 circulant gate steps into one degree-39 complex polynomial
//    P(S) = prod_t (cos(a_t/2) I + i sin(a_t/2) S) = sum_j alpha_j S^j
// ---------------------------------------------------------------------------
__global__ void coeff_kernel(const float* __restrict__ qp) {
    float pr[NTAP], pi[NTAP];
    for (int i = 0; i < NTAP; i++) { pr[i] = 0.f; pi[i] = 0.f; }
    pr[0] = 1.f;
    for (int t = 0; t < NANG; t++) {
        float a = qp[t] * 0.5f;
        float c = cosf(a), s = sinf(a);
        for (int j = t + 1; j >= 1; j--) {
            float r = pr[j], im = pi[j];
            float rm = pr[j-1], imm = pi[j-1];
            pr[j] = c*r - s*imm;      // c*p[j] + i*s*p[j-1]
            pi[j] = c*im + s*rm;
        }
        pr[0] = c*pr[0];
        pi[0] = c*pi[0];
    }
    for (int i = 0; i < NTAP; i++) { g_alpha_re[i] = pr[i]; g_alpha_im[i] = pi[i]; }
}

// ---------------------------------------------------------------------------
// 2) GEMM: classical[b,h] = sum_k x[b,k]*W[h,k]  (NT, both K-major)
//    float4 global loads restored (inputs verified readable + 16B aligned).
// ---------------------------------------------------------------------------
#define BM 128
#define BN 128
#define BK 16
#define TM 8
#define TN 8
#define GEMM_BX (HV / BN)          // 64
#define GEMM_BY (BATCH / BM)       // 8

__global__ __launch_bounds__(256)
void gemm_kernel(const float* __restrict__ x, const float* __restrict__ W) {
    __shared__ float As[BK][BM];
    __shared__ float Bs[BK][BN];

    const int bx = blockIdx.x % GEMM_BX;
    const int by = blockIdx.x / GEMM_BX;
    const int tid = threadIdx.x;
    const int tx = tid & 15;
    const int ty = tid >> 4;

    const float* xg = x + (size_t)by * BM * IN_DIM;
    const float* wg = W + (size_t)bx * BN * IN_DIM;

    float acc[TM][TN];
    #pragma unroll
    for (int i = 0; i < TM; i++)
        #pragma unroll
        for (int j = 0; j < TN; j++) acc[i][j] = 0.f;

    for (int k0 = 0; k0 < IN_DIM; k0 += BK) {
        #pragma unroll
        for (int r = 0; r < 2; r++) {
            int f   = tid + r * 256;
            int row = f >> 2;
            int c4  = (f & 3) << 2;
            float4 v = *(const float4*)(xg + (size_t)row * IN_DIM + k0 + c4);
            As[c4+0][row] = v.x; As[c4+1][row] = v.y;
            As[c4+2][row] = v.z; As[c4+3][row] = v.w;
            float4 w = *(const float4*)(wg + (size_t)row * IN_DIM + k0 + c4);
            Bs[c4+0][row] = w.x; Bs[c4+1][row] = w.y;
            Bs[c4+2][row] = w.z; Bs[c4+3][row] = w.w;
        }
        __syncthreads();

        #pragma unroll
        for (int kk = 0; kk < BK; kk++) {
            float ra[TM], rb[TN];
            #pragma unroll
            for (int i = 0; i < TM; i++) ra[i] = As[kk][ty*TM + i];
            #pragma unroll
            for (int j = 0; j < TN; j++) rb[j] = Bs[kk][tx*TN + j];
            #pragma unroll
            for (int i = 0; i < TM; i++)
                #pragma unroll
                for (int j = 0; j < TN; j++)
                    acc[i][j] += ra[i] * rb[j];
        }
        __syncthreads();
    }

    #pragma unroll
    for (int i = 0; i < TM; i++) {
        size_t row = (size_t)(by*BM + ty*TM + i);
        #pragma unroll
        for (int j = 0; j < TN; j += 4) {
            float4 v = make_float4(acc[i][j], acc[i][j+1], acc[i][j+2], acc[i][j+3]);
            *(float4*)(g_classical + row*HV + bx*BN + tx*TN + j) = v;
        }
    }
}

// ---------------------------------------------------------------------------
// 3) Per-row inverse norm (deterministic tree reduction)
// ---------------------------------------------------------------------------
__global__ void norm_kernel() {
    const int b = blockIdx.x;
    __shared__ float red[256];
    const float4* row = (const float4*)(g_classical + (size_t)b * HV);
    float s = 0.f;
    for (int i = threadIdx.x; i < HV/4; i += 256) {
        float4 v = row[i];
        s += v.x*v.x + v.y*v.y + v.z*v.z + v.w*v.w;
    }
    red[threadIdx.x] = s;
    __syncthreads();
    for (int o = 128; o > 0; o >>= 1) {
        if (threadIdx.x < o) red[threadIdx.x] += red[threadIdx.x + o];
        __syncthreads();
    }
    if (threadIdx.x == 0) g_inv_norm[b] = rsqrtf(red[0]);
}

// ---------------------------------------------------------------------------
// 4) conv: 40-tap circular convolution with Re(alpha), scaled by inv_norm,
//    writing the REAL PART of each amplitude straight into d_out.
//    d_out is 8388608 x 4B (32 MB) — verified writable for chunks 0..15.
// ---------------------------------------------------------------------------
__global__ __launch_bounds__(256)
void conv_kernel(float* __restrict__ outf, long long out_limit) {
    const long long idx = (long long)blockIdx.x * 256 + threadIdx.x;  // < BATCH*HV
    if (idx >= out_limit) return;
    const int b = (int)(idx >> 13);           // / HV
    const int n = (int)(idx & (HV - 1));
    const float* row = g_classical + ((size_t)b << 13);
    const float inv = g_inv_norm[b];

    float re = 0.f;
    #pragma unroll
    for (int j = 0; j < NTAP; j++) {
        float v = row[(n - j) & (HV - 1)];
        re += g_alpha_re[j] * v;
    }
    outf[idx] = re * inv;
}

// ---------------------------------------------------------------------------
extern "C" void kernel_launch(void* const* d_in, const int* in_sizes, int n_in,
                              void* d_out, int out_size) {
    const float* x  = (const float*)d_in[0];   // [1024,4096]
    const float* W  = (const float*)d_in[1];   // [8192,4096]
    const float* qp = (const float*)d_in[2];   // [39]
    float* outf = (float*)d_out;               // 8388608 float32 (32 MB, confirmed R11)

    cudaStreamCaptureStatus st = cudaStreamCaptureStatusNone;
    cudaStreamIsCapturing((cudaStream_t)0, &st);
    const bool capturing = (st != cudaStreamCaptureStatusNone);

    #define CK(label)                                                            \
        if (!capturing) {                                                        \
            cudaError_t e_ = cudaStreamSynchronize((cudaStream_t)0);             \
            fprintf(stderr, "[kl] %-8s : %s\n", label, cudaGetErrorString(e_));  \
        }

    coeff_kernel<<<1, 1>>>(qp);                              CK("coeff");
    gemm_kernel<<<GEMM_BX * GEMM_BY, 256>>>(x, W);           CK("gemm");
    norm_kernel<<<BATCH, 256>>>();                           CK("norm");
    conv_kernel<<<(BATCH * HV) / 256, 256>>>(outf, (long long)out_size);
                                                             CK("conv");
    #undef CK
}

// round 13
// speedup vs baseline: 2.6193x; 2.6193x over previous
#include <cuda_runtime.h>
#include <cuda_fp16.h>
#include <cstdio>
#include <cstdint>

#define BATCH   1024
#define IN_DIM  4096
#define HV      8192
#define NANG    39
#define NTAP    40

// Scratch (no allocations allowed -> __device__ globals)
__device__ float  g_classical[(size_t)BATCH*HV];     // 32 MB
__device__ float  g_inv_norm[BATCH];
__device__ float  g_alpha_re[NTAP];
__device__ float  g_alpha_im[NTAP];
__device__ __half g_xh[(size_t)BATCH*IN_DIM];        // 8 MB
__device__ __half g_wh[(size_t)HV*IN_DIM];           // 64 MB

// ---------------------------------------------------------------------------
// 0) fp32 -> fp16 conversion of x and W (vectorized, grid-stride)
// ---------------------------------------------------------------------------
__global__ void tohalf_kernel(const float* __restrict__ x, const float* __restrict__ W) {
    const long long stride = (long long)gridDim.x * blockDim.x;
    long long i0 = (long long)blockIdx.x * blockDim.x + threadIdx.x;
    const long long NX = (long long)BATCH * IN_DIM / 4;
    const long long NW = (long long)HV * IN_DIM / 4;
    for (long long j = i0; j < NX; j += stride) {
        float4 v = ((const float4*)x)[j];
        ((__half2*)g_xh)[2*j]   = __floats2half2_rn(v.x, v.y);
        ((__half2*)g_xh)[2*j+1] = __floats2half2_rn(v.z, v.w);
    }
    for (long long j = i0; j < NW; j += stride) {
        float4 v = ((const float4*)W)[j];
        ((__half2*)g_wh)[2*j]   = __floats2half2_rn(v.x, v.y);
        ((__half2*)g_wh)[2*j+1] = __floats2half2_rn(v.z, v.w);
    }
}

// ---------------------------------------------------------------------------
// 1) Collapse 39 circulant gate steps into one degree-39 complex polynomial
// ---------------------------------------------------------------------------
__global__ void coeff_kernel(const float* __restrict__ qp) {
    float pr[NTAP], pi[NTAP];
    for (int i = 0; i < NTAP; i++) { pr[i] = 0.f; pi[i] = 0.f; }
    pr[0] = 1.f;
    for (int t = 0; t < NANG; t++) {
        float a = qp[t] * 0.5f;
        float c = cosf(a), s = sinf(a);
        for (int j = t + 1; j >= 1; j--) {
            float r = pr[j], im = pi[j];
            float rm = pr[j-1], imm = pi[j-1];
            pr[j] = c*r - s*imm;
            pi[j] = c*im + s*rm;
        }
        pr[0] = c*pr[0];
        pi[0] = c*pi[0];
    }
    for (int i = 0; i < NTAP; i++) { g_alpha_re[i] = pr[i]; g_alpha_im[i] = pi[i]; }
}

// ---------------------------------------------------------------------------
// 2) Tensor-core GEMM: classical[b,h] = sum_k xh[b,k]*wh[h,k]  (fp16 in, fp32 acc)
//    BM=BN=128, BK=32, 256 thr (8 warps 2x4, 64x32 warp tile), cp.async
//    double buffer, ldmatrix + mma.sync.m16n8k16.
// ---------------------------------------------------------------------------
#define BM 128
#define BN 128
#define BK 32
#define BKP 40                     // padded smem row stride (halfs), 80B: 16B-aligned
#define GEMM_BX (HV / BN)          // 64
#define GEMM_BY (BATCH / BM)       // 8

__device__ __forceinline__ uint32_t smem_addr(const void* p) {
    return (uint32_t)__cvta_generic_to_shared(p);
}

__global__ __launch_bounds__(256, 1)
void hgemm_kernel() {
    __shared__ __align__(16) __half As[2][BM * BKP];
    __shared__ __align__(16) __half Bs[2][BN * BKP];

    const int bx = blockIdx.x % GEMM_BX;
    const int by = blockIdx.x / GEMM_BX;
    const int tid  = threadIdx.x;
    const int warp = tid >> 5;
    const int lane = tid & 31;
    const int m_warp = (warp & 1) * 64;        // 2 warps along M
    const int n_warp = (warp >> 1) * 32;       // 4 warps along N

    const __half* xg = g_xh + (size_t)by * BM * IN_DIM;
    const __half* wg = g_wh + (size_t)bx * BN * IN_DIM;

    float acc[4][4][4];
    #pragma unroll
    for (int mi = 0; mi < 4; mi++)
        #pragma unroll
        for (int nj = 0; nj < 4; nj++)
            #pragma unroll
            for (int c = 0; c < 4; c++) acc[mi][nj][c] = 0.f;

    // async tile loader: 128 rows x 32 halfs = 512 x 16B chunks per matrix
    #define LOAD_TILE(kt, buf)                                                     \
        {                                                                          \
            _Pragma("unroll")                                                      \
            for (int r = 0; r < 2; r++) {                                          \
                int ch  = tid + r * 256;                                           \
                int row = ch >> 2;                                                 \
                int c8  = (ch & 3) * 8;                                            \
                uint32_t da = smem_addr(&As[buf][row * BKP + c8]);                 \
                const __half* sa = xg + (size_t)row * IN_DIM + (kt) * BK + c8;     \
                asm volatile("cp.async.cg.shared.global [%0], [%1], 16;\n"         \
                             :: "r"(da), "l"(sa));                                 \
                uint32_t db = smem_addr(&Bs[buf][row * BKP + c8]);                 \
                const __half* sb = wg + (size_t)row * IN_DIM + (kt) * BK + c8;     \
                asm volatile("cp.async.cg.shared.global [%0], [%1], 16;\n"         \
                             :: "r"(db), "l"(sb));                                 \
            }                                                                      \
            asm volatile("cp.async.commit_group;\n" ::);                           \
        }

    LOAD_TILE(0, 0);

    const int NKT = IN_DIM / BK;   // 128
    int buf = 0;
    for (int kt = 0; kt < NKT; kt++) {
        if (kt + 1 < NKT) {
            LOAD_TILE(kt + 1, buf ^ 1);
            asm volatile("cp.async.wait_group 1;\n" ::);
        } else {
            asm volatile("cp.async.wait_group 0;\n" ::);
        }
        __syncthreads();

        #pragma unroll
        for (int ks = 0; ks < 2; ks++) {
            const int k0 = ks * 16;
            uint32_t a[4][4];
            #pragma unroll
            for (int mi = 0; mi < 4; mi++) {
                int row = m_warp + mi * 16 + ((lane >> 3) & 1) * 8 + (lane & 7);
                int kc  = k0 + (lane >> 4) * 8;
                uint32_t ad = smem_addr(&As[buf][row * BKP + kc]);
                asm volatile("ldmatrix.sync.aligned.m8n8.x4.shared.b16 {%0,%1,%2,%3}, [%4];"
                             : "=r"(a[mi][0]), "=r"(a[mi][1]), "=r"(a[mi][2]), "=r"(a[mi][3])
                             : "r"(ad));
            }
            uint32_t b[4][2];
            #pragma unroll
            for (int nj = 0; nj < 4; nj++) {
                int row = n_warp + nj * 8 + (lane & 7);
                int kc  = k0 + ((lane >> 3) & 1) * 8;
                uint32_t bd = smem_addr(&Bs[buf][row * BKP + kc]);
                asm volatile("ldmatrix.sync.aligned.m8n8.x2.shared.b16 {%0,%1}, [%2];"
                             : "=r"(b[nj][0]), "=r"(b[nj][1]) : "r"(bd));
            }
            #pragma unroll
            for (int mi = 0; mi < 4; mi++)
                #pragma unroll
                for (int nj = 0; nj < 4; nj++)
                    asm volatile("mma.sync.aligned.m16n8k16.row.col.f32.f16.f16.f32 "
                                 "{%0,%1,%2,%3}, {%4,%5,%6,%7}, {%8,%9}, {%0,%1,%2,%3};"
                                 : "+f"(acc[mi][nj][0]), "+f"(acc[mi][nj][1]),
                                   "+f"(acc[mi][nj][2]), "+f"(acc[mi][nj][3])
                                 : "r"(a[mi][0]), "r"(a[mi][1]), "r"(a[mi][2]), "r"(a[mi][3]),
                                   "r"(b[nj][0]), "r"(b[nj][1]));
        }
        __syncthreads();
        buf ^= 1;
    }

    // Epilogue: c0,c1 -> (m, n..n+1); c2,c3 -> (m+8, n..n+1)
    const int tg = lane & 3, grp = lane >> 2;
    #pragma unroll
    for (int mi = 0; mi < 4; mi++) {
        #pragma unroll
        for (int nj = 0; nj < 4; nj++) {
            int m = by * BM + m_warp + mi * 16 + grp;
            int n = bx * BN + n_warp + nj * 8 + tg * 2;
            *(float2*)&g_classical[(size_t)m * HV + n] =
                make_float2(acc[mi][nj][0], acc[mi][nj][1]);
            *(float2*)&g_classical[(size_t)(m + 8) * HV + n] =
                make_float2(acc[mi][nj][2], acc[mi][nj][3]);
        }
    }
    #undef LOAD_TILE
}

// ---------------------------------------------------------------------------
// 3) Per-row inverse norm (deterministic tree reduction)
// ---------------------------------------------------------------------------
__global__ void norm_kernel() {
    const int b = blockIdx.x;
    __shared__ float red[256];
    const float4* row = (const float4*)(g_classical + (size_t)b * HV);
    float s = 0.f;
    for (int i = threadIdx.x; i < HV/4; i += 256) {
        float4 v = row[i];
        s += v.x*v.x + v.y*v.y + v.z*v.z + v.w*v.w;
    }
    red[threadIdx.x] = s;
    __syncthreads();
    for (int o = 128; o > 0; o >>= 1) {
        if (threadIdx.x < o) red[threadIdx.x] += red[threadIdx.x + o];
        __syncthreads();
    }
    if (threadIdx.x == 0) g_inv_norm[b] = rsqrtf(red[0]);
}

// ---------------------------------------------------------------------------
// 4) conv: 40-tap circular convolution with Re(alpha) -> real part into d_out
// ---------------------------------------------------------------------------
__global__ __launch_bounds__(256)
void conv_kernel(float* __restrict__ outf, long long out_limit) {
    const long long idx = (long long)blockIdx.x * 256 + threadIdx.x;
    if (idx >= out_limit) return;
    const int b = (int)(idx >> 13);
    const int n = (int)(idx & (HV - 1));
    const float* row = g_classical + ((size_t)b << 13);
    const float inv = g_inv_norm[b];

    float re = 0.f;
    #pragma unroll
    for (int j = 0; j < NTAP; j++) {
        float v = row[(n - j) & (HV - 1)];
        re += g_alpha_re[j] * v;
    }
    outf[idx] = re * inv;
}

// ---------------------------------------------------------------------------
extern "C" void kernel_launch(void* const* d_in, const int* in_sizes, int n_in,
                              void* d_out, int out_size) {
    const float* x  = (const float*)d_in[0];   // [1024,4096]
    const float* W  = (const float*)d_in[1];   // [8192,4096]
    const float* qp = (const float*)d_in[2];   // [39]
    float* outf = (float*)d_out;               // 8388608 float32 (real parts)

    cudaStreamCaptureStatus st = cudaStreamCaptureStatusNone;
    cudaStreamIsCapturing((cudaStream_t)0, &st);
    const bool capturing = (st != cudaStreamCaptureStatusNone);

    #define CK(label)                                                            \
        if (!capturing) {                                                        \
            cudaError_t e_ = cudaStreamSynchronize((cudaStream_t)0);             \
            fprintf(stderr, "[kl] %-8s : %s\n", label, cudaGetErrorString(e_));  \
        }

    tohalf_kernel<<<2048, 256>>>(x, W);                      CK("tohalf");
    coeff_kernel<<<1, 1>>>(qp);                              CK("coeff");
    hgemm_kernel<<<GEMM_BX * GEMM_BY, 256>>>();              CK("hgemm");
    norm_kernel<<<BATCH, 256>>>();                           CK("norm");
    conv_kernel<<<(BATCH * HV) / 256, 256>>>(outf, (long long)out_size);
                                                             CK("conv");
    #undef CK
}

// round 15
// speedup vs baseline: 4.6936x; 1.7920x over previous
#include <cuda_runtime.h>
#include <cuda_fp16.h>
#include <cstdio>
#include <cstdint>

#define BATCH   1024
#define IN_DIM  4096
#define HV      8192
#define NANG    39
#define NTAP    40

// Scratch (no allocations allowed -> __device__ globals)
__device__ float  g_classical[(size_t)BATCH*HV];     // 32 MB
__device__ float  g_inv_norm[BATCH];
__device__ float  g_alpha_re[NTAP];
__device__ float  g_alpha_im[NTAP];
__device__ __align__(128) __half g_xh[(size_t)BATCH*IN_DIM];   // 8 MB
__device__ __align__(128) __half g_wh[(size_t)HV*IN_DIM];      // 64 MB

__device__ __forceinline__ uint32_t smem_u32(const void* p) {
    return (uint32_t)__cvta_generic_to_shared(p);
}

// ---------------------------------------------------------------------------
// 0) fp32 -> fp16 conversion of x and W
// ---------------------------------------------------------------------------
__global__ void tohalf_kernel(const float* __restrict__ x, const float* __restrict__ W) {
    const long long stride = (long long)gridDim.x * blockDim.x;
    long long i0 = (long long)blockIdx.x * blockDim.x + threadIdx.x;
    const long long NX = (long long)BATCH * IN_DIM / 4;
    const long long NW = (long long)HV * IN_DIM / 4;
    for (long long j = i0; j < NX; j += stride) {
        float4 v = ((const float4*)x)[j];
        ((__half2*)g_xh)[2*j]   = __floats2half2_rn(v.x, v.y);
        ((__half2*)g_xh)[2*j+1] = __floats2half2_rn(v.z, v.w);
    }
    for (long long j = i0; j < NW; j += stride) {
        float4 v = ((const float4*)W)[j];
        ((__half2*)g_wh)[2*j]   = __floats2half2_rn(v.x, v.y);
        ((__half2*)g_wh)[2*j+1] = __floats2half2_rn(v.z, v.w);
    }
}

// ---------------------------------------------------------------------------
// 1) Collapse 39 circulant gate steps into one degree-39 complex polynomial
// ---------------------------------------------------------------------------
__global__ void coeff_kernel(const float* __restrict__ qp) {
    float pr[NTAP], pi[NTAP];
    for (int i = 0; i < NTAP; i++) { pr[i] = 0.f; pi[i] = 0.f; }
    pr[0] = 1.f;
    for (int t = 0; t < NANG; t++) {
        float a = qp[t] * 0.5f;
        float c = cosf(a), s = sinf(a);
        for (int j = t + 1; j >= 1; j--) {
            float r = pr[j], im = pi[j];
            float rm = pr[j-1], imm = pi[j-1];
            pr[j] = c*r - s*imm;
            pi[j] = c*im + s*rm;
        }
        pr[0] = c*pr[0];
        pi[0] = c*pi[0];
    }
    for (int i = 0; i < NTAP; i++) { g_alpha_re[i] = pr[i]; g_alpha_im[i] = pi[i]; }
}

// ---------------------------------------------------------------------------
// 2) HMMA GEMM: classical[b,h] = sum_k xh[b,k]*wh[h,k]  (fp16 in, fp32 acc)
//    BM=128, BN=256, BK=32, 3-stage cp.async, ONE sync per K-iter,
//    8 warps (2Mx4N), 64x64 warp tile, ldmatrix.x4 for both A and B.
// ---------------------------------------------------------------------------
#define BM 128
#define BN 256
#define BK 32
#define BKP 40                     // padded smem row stride (halfs)
#define STAGES 3
#define GEMM_BX (HV / BN)          // 32
#define GEMM_BY (BATCH / BM)       // 8
#define NKT (IN_DIM / BK)          // 128
#define A_STAGE (BM * BKP)         // 5120 halfs
#define B_STAGE (BN * BKP)         // 10240 halfs
#define SM_TOTAL (STAGES * (A_STAGE + B_STAGE) * 2)   // 92160 B

__global__ __launch_bounds__(256, 1)
void hgemm_kernel() {
    extern __shared__ __align__(16) __half sm[];
    __half* As = sm;                           // [STAGES][A_STAGE]
    __half* Bs = sm + STAGES * A_STAGE;        // [STAGES][B_STAGE]

    const int bx = blockIdx.x % GEMM_BX;
    const int by = blockIdx.x / GEMM_BX;
    const int tid  = threadIdx.x;
    const int warp = tid >> 5;
    const int lane = tid & 31;
    const int m_warp = (warp & 1) * 64;        // 2 warps along M
    const int n_warp = (warp >> 1) * 64;       // 4 warps along N

    const __half* xg = g_xh + (size_t)by * BM * IN_DIM;
    const __half* wg = g_wh + (size_t)bx * BN * IN_DIM;

    float acc[4][8][4];
    #pragma unroll
    for (int mi = 0; mi < 4; mi++)
        #pragma unroll
        for (int nj = 0; nj < 8; nj++)
            #pragma unroll
            for (int c = 0; c < 4; c++) acc[mi][nj][c] = 0.f;

    // A: 128x32h = 512 x16B chunks (2/thread); B: 256x32h = 1024 (4/thread)
    #define LOAD_TILE(kt, buf)                                                     \
        {                                                                          \
            _Pragma("unroll")                                                      \
            for (int r = 0; r < 2; r++) {                                          \
                int ch  = tid + r * 256;                                           \
                int row = ch >> 2;                                                 \
                int c8  = (ch & 3) * 8;                                            \
                uint32_t da = smem_u32(&As[(buf) * A_STAGE + row * BKP + c8]);     \
                const __half* sa = xg + (size_t)row * IN_DIM + (kt) * BK + c8;     \
                asm volatile("cp.async.cg.shared.global [%0], [%1], 16;\n"         \
                             :: "r"(da), "l"(sa));                                 \
            }                                                                      \
            _Pragma("unroll")                                                      \
            for (int r = 0; r < 4; r++) {                                          \
                int ch  = tid + r * 256;                                           \
                int row = ch >> 2;                                                 \
                int c8  = (ch & 3) * 8;                                            \
                uint32_t db = smem_u32(&Bs[(buf) * B_STAGE + row * BKP + c8]);     \
                const __half* sb = wg + (size_t)row * IN_DIM + (kt) * BK + c8;     \
                asm volatile("cp.async.cg.shared.global [%0], [%1], 16;\n"         \
                             :: "r"(db), "l"(sb));                                 \
            }                                                                      \
            asm volatile("cp.async.commit_group;\n" ::);                           \
        }

    LOAD_TILE(0, 0);
    LOAD_TILE(1, 1);

    for (int kt = 0; kt < NKT; kt++) {
        const int buf = kt % STAGES;
        if (kt == NKT - 1) asm volatile("cp.async.wait_group 0;\n" ::);
        else               asm volatile("cp.async.wait_group 1;\n" ::);
        __syncthreads();           // stage `kt` visible; buffer (kt-1)%S now free

        if (kt + 2 < NKT) LOAD_TILE(kt + 2, (kt + 2) % STAGES);

        const __half* Ab = &As[buf * A_STAGE];
        const __half* Bb = &Bs[buf * B_STAGE];

        #pragma unroll
        for (int ks = 0; ks < 2; ks++) {
            const int k0 = ks * 16;
            const int lrow = ((lane >> 3) & 1) * 8 + (lane & 7);
            const int lcol = k0 + (lane >> 4) * 8;
            uint32_t a[4][4];
            #pragma unroll
            for (int mi = 0; mi < 4; mi++) {
                uint32_t ad = smem_u32(&Ab[(m_warp + mi * 16 + lrow) * BKP + lcol]);
                asm volatile("ldmatrix.sync.aligned.m8n8.x4.shared.b16 {%0,%1,%2,%3}, [%4];"
                             : "=r"(a[mi][0]), "=r"(a[mi][1]), "=r"(a[mi][2]), "=r"(a[mi][3])
                             : "r"(ad));
            }
            uint32_t b4[4][4];
            #pragma unroll
            for (int np = 0; np < 4; np++) {   // pairs of n8 tiles: 16 n-rows each
                uint32_t bd = smem_u32(&Bb[(n_warp + np * 16 + lrow) * BKP + lcol]);
                asm volatile("ldmatrix.sync.aligned.m8n8.x4.shared.b16 {%0,%1,%2,%3}, [%4];"
                             : "=r"(b4[np][0]), "=r"(b4[np][1]), "=r"(b4[np][2]), "=r"(b4[np][3])
                             : "r"(bd));
            }
            #pragma unroll
            for (int mi = 0; mi < 4; mi++)
                #pragma unroll
                for (int nj = 0; nj < 8; nj++) {
                    const uint32_t b0 = b4[nj >> 1][nj & 1];       // n k0-7
                    const uint32_t b1 = b4[nj >> 1][(nj & 1) + 2]; // n k8-15
                    asm volatile("mma.sync.aligned.m16n8k16.row.col.f32.f16.f16.f32 "
                                 "{%0,%1,%2,%3}, {%4,%5,%6,%7}, {%8,%9}, {%0,%1,%2,%3};"
                                 : "+f"(acc[mi][nj][0]), "+f"(acc[mi][nj][1]),
                                   "+f"(acc[mi][nj][2]), "+f"(acc[mi][nj][3])
                                 : "r"(a[mi][0]), "r"(a[mi][1]), "r"(a[mi][2]), "r"(a[mi][3]),
                                   "r"(b0), "r"(b1));
                }
        }
    }

    // Epilogue: c0,c1 -> (m, n..n+1); c2,c3 -> (m+8, n..n+1)
    const int tg = lane & 3, grp = lane >> 2;
    #pragma unroll
    for (int mi = 0; mi < 4; mi++) {
        #pragma unroll
        for (int nj = 0; nj < 8; nj++) {
            int m = by * BM + m_warp + mi * 16 + grp;
            int n = bx * BN + n_warp + nj * 8 + tg * 2;
            *(float2*)&g_classical[(size_t)m * HV + n] =
                make_float2(acc[mi][nj][0], acc[mi][nj][1]);
            *(float2*)&g_classical[(size_t)(m + 8) * HV + n] =
                make_float2(acc[mi][nj][2], acc[mi][nj][3]);
        }
    }
    #undef LOAD_TILE
}

// ---------------------------------------------------------------------------
// 3) Per-row inverse norm (deterministic tree reduction)
// ---------------------------------------------------------------------------
__global__ void norm_kernel() {
    const int b = blockIdx.x;
    __shared__ float red[256];
    const float4* row = (const float4*)(g_classical + (size_t)b * HV);
    float s = 0.f;
    for (int i = threadIdx.x; i < HV/4; i += 256) {
        float4 v = row[i];
        s += v.x*v.x + v.y*v.y + v.z*v.z + v.w*v.w;
    }
    red[threadIdx.x] = s;
    __syncthreads();
    for (int o = 128; o > 0; o >>= 1) {
        if (threadIdx.x < o) red[threadIdx.x] += red[threadIdx.x + o];
        __syncthreads();
    }
    if (threadIdx.x == 0) g_inv_norm[b] = rsqrtf(red[0]);
}

// ---------------------------------------------------------------------------
// 4) conv: 40-tap circular convolution via shared tile + halo
// ---------------------------------------------------------------------------
#define SEG 2048
#define NSEGB (HV / SEG)           // 4

__global__ __launch_bounds__(256)
void conv_kernel(float* __restrict__ outf) {
    const int seg = blockIdx.x & (NSEGB - 1);
    const int b   = blockIdx.x >> 2;
    __shared__ float s[SEG + NTAP];
    __shared__ float alr[NTAP];
    const int tid = threadIdx.x;

    if (tid < NTAP) alr[tid] = g_alpha_re[tid];
    const float* row = g_classical + ((size_t)b << 13);
    const int base = seg * SEG - NTAP;            // left circular halo
    for (int i = tid; i < SEG + NTAP; i += 256) {
        int g = (base + i) & (HV - 1);
        s[i] = row[g];
    }
    __syncthreads();

    const float inv = g_inv_norm[b];
    #pragma unroll
    for (int k = 0; k < SEG/256; k++) {
        int nl = tid + k * 256;
        float re = 0.f;
        #pragma unroll
        for (int j = 0; j < NTAP; j++)
            re += alr[j] * s[nl + NTAP - j];
        outf[((size_t)b << 13) + seg * SEG + nl] = re * inv;
    }
}

// ---------------------------------------------------------------------------
extern "C" void kernel_launch(void* const* d_in, const int* in_sizes, int n_in,
                              void* d_out, int out_size) {
    const float* x  = (const float*)d_in[0];   // [1024,4096]
    const float* W  = (const float*)d_in[1];   // [8192,4096]
    const float* qp = (const float*)d_in[2];   // [39]
    float* outf = (float*)d_out;               // 8388608 float32 (real parts)

    cudaStreamCaptureStatus st = cudaStreamCaptureStatusNone;
    cudaStreamIsCapturing((cudaStream_t)0, &st);
    const bool capturing = (st != cudaStreamCaptureStatusNone);

    #define CK(label)                                                            \
        if (!capturing) {                                                        \
            cudaError_t e_ = cudaStreamSynchronize((cudaStream_t)0);             \
            fprintf(stderr, "[kl] %-8s : %s\n", label, cudaGetErrorString(e_));  \
        }

    cudaFuncSetAttribute(hgemm_kernel,
                         cudaFuncAttributeMaxDynamicSharedMemorySize, SM_TOTAL);

    tohalf_kernel<<<2048, 256>>>(x, W);                      CK("tohalf");
    coeff_kernel<<<1, 1>>>(qp);                              CK("coeff");
    hgemm_kernel<<<GEMM_BX * GEMM_BY, 256, SM_TOTAL>>>();    CK("hgemm");
    norm_kernel<<<BATCH, 256>>>();                           CK("norm");
    conv_kernel<<<BATCH * NSEGB, 256>>>(outf);               CK("conv");
    #undef CK
}

// round 16
// speedup vs baseline: 5.0280x; 1.0712x over previous
#include <cuda_runtime.h>
#include <cuda_fp16.h>
#include <cstdio>
#include <cstdint>

#define BATCH   1024
#define IN_DIM  4096
#define HV      8192
#define NANG    39
#define NTAP    40

// Scratch (no allocations allowed -> __device__ globals)
__device__ float  g_classical[(size_t)BATCH*HV];     // 32 MB
__device__ float  g_alpha_re[NTAP];
__device__ float  g_alpha_im[NTAP];
__device__ __align__(128) __half g_xh[(size_t)BATCH*IN_DIM];   // 8 MB
__device__ __align__(128) __half g_wh[(size_t)HV*IN_DIM];      // 64 MB

__device__ __forceinline__ uint32_t smem_u32(const void* p) {
    return (uint32_t)__cvta_generic_to_shared(p);
}

// ---------------------------------------------------------------------------
// 0) fp32 -> fp16 conversion of x and W
// ---------------------------------------------------------------------------
__global__ void tohalf_kernel(const float* __restrict__ x, const float* __restrict__ W) {
    const long long stride = (long long)gridDim.x * blockDim.x;
    long long i0 = (long long)blockIdx.x * blockDim.x + threadIdx.x;
    const long long NX = (long long)BATCH * IN_DIM / 4;
    const long long NW = (long long)HV * IN_DIM / 4;
    for (long long j = i0; j < NX; j += stride) {
        float4 v = ((const float4*)x)[j];
        ((__half2*)g_xh)[2*j]   = __floats2half2_rn(v.x, v.y);
        ((__half2*)g_xh)[2*j+1] = __floats2half2_rn(v.z, v.w);
    }
    for (long long j = i0; j < NW; j += stride) {
        float4 v = ((const float4*)W)[j];
        ((__half2*)g_wh)[2*j]   = __floats2half2_rn(v.x, v.y);
        ((__half2*)g_wh)[2*j+1] = __floats2half2_rn(v.z, v.w);
    }
}

// ---------------------------------------------------------------------------
// 1) Collapse 39 circulant gate steps into one degree-39 complex polynomial
// ---------------------------------------------------------------------------
__global__ void coeff_kernel(const float* __restrict__ qp) {
    float pr[NTAP], pi[NTAP];
    for (int i = 0; i < NTAP; i++) { pr[i] = 0.f; pi[i] = 0.f; }
    pr[0] = 1.f;
    for (int t = 0; t < NANG; t++) {
        float a = qp[t] * 0.5f;
        float c = cosf(a), s = sinf(a);
        for (int j = t + 1; j >= 1; j--) {
            float r = pr[j], im = pi[j];
            float rm = pr[j-1], imm = pi[j-1];
            pr[j] = c*r - s*imm;
            pi[j] = c*im + s*rm;
        }
        pr[0] = c*pr[0];
        pi[0] = c*pi[0];
    }
    for (int i = 0; i < NTAP; i++) { g_alpha_re[i] = pr[i]; g_alpha_im[i] = pi[i]; }
}

// ---------------------------------------------------------------------------
// 2) HMMA GEMM: BM=128, BN=256, BK=32, 4-stage cp.async, one sync per K-iter,
//    8 warps (2Mx4N), 64x64 warp tile, ldmatrix.x4 for both A and B.
// ---------------------------------------------------------------------------
#define BM 128
#define BN 256
#define BK 32
#define BKP 40                     // padded smem row stride (halfs)
#define STAGES 4
#define GEMM_BX (HV / BN)          // 32
#define GEMM_BY (BATCH / BM)       // 8
#define NKT (IN_DIM / BK)          // 128
#define A_STAGE (BM * BKP)         // 5120 halfs
#define B_STAGE (BN * BKP)         // 10240 halfs
#define SM_TOTAL (STAGES * (A_STAGE + B_STAGE) * 2)   // 122880 B

__global__ __launch_bounds__(256, 1)
void hgemm_kernel() {
    extern __shared__ __align__(16) __half sm[];
    __half* As = sm;                           // [STAGES][A_STAGE]
    __half* Bs = sm + STAGES * A_STAGE;        // [STAGES][B_STAGE]

    const int bx = blockIdx.x % GEMM_BX;
    const int by = blockIdx.x / GEMM_BX;
    const int tid  = threadIdx.x;
    const int warp = tid >> 5;
    const int lane = tid & 31;
    const int m_warp = (warp & 1) * 64;
    const int n_warp = (warp >> 1) * 64;

    const __half* xg = g_xh + (size_t)by * BM * IN_DIM;
    const __half* wg = g_wh + (size_t)bx * BN * IN_DIM;

    float acc[4][8][4];
    #pragma unroll
    for (int mi = 0; mi < 4; mi++)
        #pragma unroll
        for (int nj = 0; nj < 8; nj++)
            #pragma unroll
            for (int c = 0; c < 4; c++) acc[mi][nj][c] = 0.f;

    #define LOAD_TILE(kt, buf)                                                     \
        {                                                                          \
            _Pragma("unroll")                                                      \
            for (int r = 0; r < 2; r++) {                                          \
                int ch  = tid + r * 256;                                           \
                int row = ch >> 2;                                                 \
                int c8  = (ch & 3) * 8;                                            \
                uint32_t da = smem_u32(&As[(buf) * A_STAGE + row * BKP + c8]);     \
                const __half* sa = xg + (size_t)row * IN_DIM + (kt) * BK + c8;     \
                asm volatile("cp.async.cg.shared.global [%0], [%1], 16;\n"         \
                             :: "r"(da), "l"(sa));                                 \
            }                                                                      \
            _Pragma("unroll")                                                      \
            for (int r = 0; r < 4; r++) {                                          \
                int ch  = tid + r * 256;                                           \
                int row = ch >> 2;                                                 \
                int c8  = (ch & 3) * 8;                                            \
                uint32_t db = smem_u32(&Bs[(buf) * B_STAGE + row * BKP + c8]);     \
                const __half* sb = wg + (size_t)row * IN_DIM + (kt) * BK + c8;     \
                asm volatile("cp.async.cg.shared.global [%0], [%1], 16;\n"         \
                             :: "r"(db), "l"(sb));                                 \
            }                                                                      \
            asm volatile("cp.async.commit_group;\n" ::);                           \
        }

    LOAD_TILE(0, 0);
    LOAD_TILE(1, 1);
    LOAD_TILE(2, 2);

    for (int kt = 0; kt < NKT; kt++) {
        const int buf = kt & (STAGES - 1);
        if      (kt >= NKT - 1) asm volatile("cp.async.wait_group 0;\n" ::);
        else if (kt == NKT - 2) asm volatile("cp.async.wait_group 1;\n" ::);
        else                    asm volatile("cp.async.wait_group 2;\n" ::);
        __syncthreads();

        if (kt + 3 < NKT) LOAD_TILE(kt + 3, (kt + 3) & (STAGES - 1));

        const __half* Ab = &As[buf * A_STAGE];
        const __half* Bb = &Bs[buf * B_STAGE];

        #pragma unroll
        for (int ks = 0; ks < 2; ks++) {
            const int k0 = ks * 16;
            const int lrow = ((lane >> 3) & 1) * 8 + (lane & 7);
            const int lcol = k0 + (lane >> 4) * 8;
            uint32_t a[4][4];
            #pragma unroll
            for (int mi = 0; mi < 4; mi++) {
                uint32_t ad = smem_u32(&Ab[(m_warp + mi * 16 + lrow) * BKP + lcol]);
                asm volatile("ldmatrix.sync.aligned.m8n8.x4.shared.b16 {%0,%1,%2,%3}, [%4];"
                             : "=r"(a[mi][0]), "=r"(a[mi][1]), "=r"(a[mi][2]), "=r"(a[mi][3])
                             : "r"(ad));
            }
            uint32_t b4[4][4];
            #pragma unroll
            for (int np = 0; np < 4; np++) {
                uint32_t bd = smem_u32(&Bb[(n_warp + np * 16 + lrow) * BKP + lcol]);
                asm volatile("ldmatrix.sync.aligned.m8n8.x4.shared.b16 {%0,%1,%2,%3}, [%4];"
                             : "=r"(b4[np][0]), "=r"(b4[np][1]), "=r"(b4[np][2]), "=r"(b4[np][3])
                             : "r"(bd));
            }
            #pragma unroll
            for (int mi = 0; mi < 4; mi++)
                #pragma unroll
                for (int nj = 0; nj < 8; nj++) {
                    const uint32_t b0 = b4[nj >> 1][nj & 1];
                    const uint32_t b1 = b4[nj >> 1][(nj & 1) + 2];
                    asm volatile("mma.sync.aligned.m16n8k16.row.col.f32.f16.f16.f32 "
                                 "{%0,%1,%2,%3}, {%4,%5,%6,%7}, {%8,%9}, {%0,%1,%2,%3};"
                                 : "+f"(acc[mi][nj][0]), "+f"(acc[mi][nj][1]),
                                   "+f"(acc[mi][nj][2]), "+f"(acc[mi][nj][3])
                                 : "r"(a[mi][0]), "r"(a[mi][1]), "r"(a[mi][2]), "r"(a[mi][3]),
                                   "r"(b0), "r"(b1));
                }
        }
    }

    const int tg = lane & 3, grp = lane >> 2;
    #pragma unroll
    for (int mi = 0; mi < 4; mi++) {
        #pragma unroll
        for (int nj = 0; nj < 8; nj++) {
            int m = by * BM + m_warp + mi * 16 + grp;
            int n = bx * BN + n_warp + nj * 8 + tg * 2;
            *(float2*)&g_classical[(size_t)m * HV + n] =
                make_float2(acc[mi][nj][0], acc[mi][nj][1]);
            *(float2*)&g_classical[(size_t)(m + 8) * HV + n] =
                make_float2(acc[mi][nj][2], acc[mi][nj][3]);
        }
    }
    #undef LOAD_TILE
}

// ---------------------------------------------------------------------------
// 3) Fused norm + conv: one block per batch row.
//    Phase A: stage row (+40 circular halo) in smem, accumulate sum of squares
//             during the load, deterministic tree reduce -> inv_norm.
//    Phase B: each thread computes 4 consecutive outputs from 11 aligned
//             float4 smem blocks using a 4-phase shifted coefficient table.
//    out[n] = inv * sum_{j=0..39} alpha_re[j] * row[(n-j) mod 8192]
// ---------------------------------------------------------------------------
__global__ __launch_bounds__(256)
void normconv_kernel(float* __restrict__ outf) {
    const int b = blockIdx.x;
    __shared__ float4 s4[2058];                 // s[40+n] = row[n], n=0..8191
    __shared__ float4 cal[4][11];               // coeff table per (n mod 4) phase
    __shared__ float  red[256];
    float* s = (float*)s4;
    const int tid = threadIdx.x;

    const float4* row4 = (const float4*)(g_classical + ((size_t)b << 13));
    float accq = 0.f;
    #pragma unroll
    for (int g = 0; g < 8; g++) {
        int i = tid + g * 256;                  // 2048 float4 per row
        float4 v = row4[i];
        s4[10 + i] = v;
        accq += v.x*v.x + v.y*v.y + v.z*v.z + v.w*v.w;
    }
    if (tid < 40) s[tid] = ((const float*)row4)[8152 + tid];   // circular halo
    if (tid < 176) {                            // cal[m][q].r = alpha[m+40-4q-r]
        int m = tid / 44, rem = tid % 44, q = rem >> 2, r = rem & 3;
        int j = m + 40 - 4*q - r;
        ((float*)cal)[tid] = (j >= 0 && j < NTAP) ? g_alpha_re[j] : 0.f;
    }
    red[tid] = accq;
    __syncthreads();
    for (int o = 128; o > 0; o >>= 1) {
        if (tid < o) red[tid] += red[tid + o];
        __syncthreads();
    }
    const float inv = rsqrtf(red[0]);

    float4* out4 = (float4*)(outf + ((size_t)b << 13));
    #pragma unroll
    for (int g = 0; g < 8; g++) {
        int T = tid + g * 256;                  // output group: n = 4T..4T+3
        float r0 = 0.f, r1 = 0.f, r2 = 0.f, r3 = 0.f;
        #pragma unroll
        for (int q = 0; q < 11; q++) {
            float4 v = s4[T + q];
            float4 c0 = cal[0][q], c1 = cal[1][q], c2 = cal[2][q], c3 = cal[3][q];
            r0 = fmaf(v.x, c0.x, fmaf(v.y, c0.y, fmaf(v.z, c0.z, fmaf(v.w, c0.w, r0))));
            r1 = fmaf(v.x, c1.x, fmaf(v.y, c1.y, fmaf(v.z, c1.z, fmaf(v.w, c1.w, r1))));
            r2 = fmaf(v.x, c2.x, fmaf(v.y, c2.y, fmaf(v.z, c2.z, fmaf(v.w, c2.w, r2))));
            r3 = fmaf(v.x, c3.x, fmaf(v.y, c3.y, fmaf(v.z, c3.z, fmaf(v.w, c3.w, r3))));
        }
        out4[T] = make_float4(r0 * inv, r1 * inv, r2 * inv, r3 * inv);
    }
}

// ---------------------------------------------------------------------------
extern "C" void kernel_launch(void* const* d_in, const int* in_sizes, int n_in,
                              void* d_out, int out_size) {
    const float* x  = (const float*)d_in[0];   // [1024,4096]
    const float* W  = (const float*)d_in[1];   // [8192,4096]
    const float* qp = (const float*)d_in[2];   // [39]
    float* outf = (float*)d_out;               // 8388608 float32 (real parts)

    cudaStreamCaptureStatus st = cudaStreamCaptureStatusNone;
    cudaStreamIsCapturing((cudaStream_t)0, &st);
    const bool capturing = (st != cudaStreamCaptureStatusNone);

    #define CK(label)                                                            \
        if (!capturing) {                                                        \
            cudaError_t e_ = cudaStreamSynchronize((cudaStream_t)0);             \
            fprintf(stderr, "[kl] %-8s : %s\n", label, cudaGetErrorString(e_));  \
        }

    cudaFuncSetAttribute(hgemm_kernel,
                         cudaFuncAttributeMaxDynamicSharedMemorySize, SM_TOTAL);

    tohalf_kernel<<<2048, 256>>>(x, W);                      CK("tohalf");
    coeff_kernel<<<1, 1>>>(qp);                              CK("coeff");
    hgemm_kernel<<<GEMM_BX * GEMM_BY, 256, SM_TOTAL>>>();    CK("hgemm");
    normconv_kernel<<<BATCH, 256>>>(outf);                   CK("normconv");
    #undef CK
}